// round 3
// baseline (speedup 1.0000x reference)
#include <cuda_runtime.h>
#include <cuda_bf16.h>
#include <math.h>

#define NN 50000
#define EE 1600000
#define DIM 128
#define HEADS 4
#define ODIM 32
#define ALPHA 0.2f

// ---------------- device scratch (no allocation allowed) ----------------
__device__ __align__(16) float g_H[NN * DIM];           // 25.6 MB projected features
__device__ __align__(16) float g_Hs[NN * HEADS];        // per-node src scores
__device__ __align__(16) float g_Ht[NN * HEADS];        // per-node tgt scores
__device__ __align__(16) float g_denom[NN * HEADS];     // softmax denominators
__device__ __align__(16) float g_expe[(size_t)EE * HEADS]; // 25.6 MB exp(e - max)
__device__ unsigned g_maxenc;                           // order-preserving max

// order-preserving float<->uint encoding for atomicMax on arbitrary-sign floats
__device__ __forceinline__ unsigned enc_f(float f) {
    unsigned u = __float_as_uint(f);
    return (u & 0x80000000u) ? ~u : (u | 0x80000000u);
}
__device__ __forceinline__ float dec_f(unsigned u) {
    return (u & 0x80000000u) ? __uint_as_float(u ^ 0x80000000u)
                             : __uint_as_float(~u);
}

__device__ __forceinline__ void red_add_v4(float* p, float4 v) {
    asm volatile("red.global.add.v4.f32 [%0], {%1,%2,%3,%4};"
                 :: "l"(p), "f"(v.x), "f"(v.y), "f"(v.z), "f"(v.w)
                 : "memory");
}

// ---------------- K0: init ----------------
__global__ void init_kernel(float* out) {
    int i = blockIdx.x * blockDim.x + threadIdx.x;
    if (i == 0) g_maxenc = 0u;
    if (i < NN * DIM) out[i] = 0.0f;
    if (i < NN * HEADS) g_denom[i] = 0.0f;
}

// ---------------- K1: GEMM  H = X @ W  (N x 128) * (128 x 128) ----------------
__global__ __launch_bounds__(256) void gemm_kernel(const float* __restrict__ X,
                                                   const float* __restrict__ W) {
    __shared__ __align__(16) float Xs[16][132]; // [k][m], padded row (528B)
    __shared__ __align__(16) float Ws[16][128]; // [k][n]
    const int m0 = blockIdx.x * 128;
    const int tid = threadIdx.x;
    const int tx = tid & 15;        // col group
    const int ty = tid >> 4;        // row group
    float acc[8][8];
#pragma unroll
    for (int i = 0; i < 8; i++)
#pragma unroll
        for (int j = 0; j < 8; j++) acc[i][j] = 0.0f;

    for (int k0 = 0; k0 < DIM; k0 += 16) {
#pragma unroll
        for (int j = 0; j < 2; j++) {
            int s = tid * 2 + j;              // 0..511
            int m = s >> 2;
            int kk4 = (s & 3) * 4;
            float4 v = make_float4(0.f, 0.f, 0.f, 0.f);
            int gm = m0 + m;
            if (gm < NN) v = *(const float4*)(X + (size_t)gm * DIM + k0 + kk4);
            Xs[kk4 + 0][m] = v.x;
            Xs[kk4 + 1][m] = v.y;
            Xs[kk4 + 2][m] = v.z;
            Xs[kk4 + 3][m] = v.w;
            int wk = s >> 5;
            int wc = (s & 31) * 4;
            *(float4*)&Ws[wk][wc] = *(const float4*)(W + (size_t)(k0 + wk) * DIM + wc);
        }
        __syncthreads();
#pragma unroll
        for (int kk = 0; kk < 16; kk++) {
            float a[8], b[8];
            *(float4*)(a)     = *(float4*)&Xs[kk][ty * 8];
            *(float4*)(a + 4) = *(float4*)&Xs[kk][ty * 8 + 4];
            *(float4*)(b)     = *(float4*)&Ws[kk][tx * 8];
            *(float4*)(b + 4) = *(float4*)&Ws[kk][tx * 8 + 4];
#pragma unroll
            for (int i = 0; i < 8; i++)
#pragma unroll
                for (int j = 0; j < 8; j++) acc[i][j] = fmaf(a[i], b[j], acc[i][j]);
        }
        __syncthreads();
    }
#pragma unroll
    for (int i = 0; i < 8; i++) {
        int gm = m0 + ty * 8 + i;
        if (gm < NN) {
            float4 v0 = make_float4(acc[i][0], acc[i][1], acc[i][2], acc[i][3]);
            float4 v1 = make_float4(acc[i][4], acc[i][5], acc[i][6], acc[i][7]);
            *(float4*)(g_H + (size_t)gm * DIM + tx * 8)     = v0;
            *(float4*)(g_H + (size_t)gm * DIM + tx * 8 + 4) = v1;
        }
    }
}

// ---------------- K2: per-node attention scores Hs / Ht ----------------
__global__ void score_kernel(const float* __restrict__ Al, const float* __restrict__ Ar) {
    int idx = blockIdx.x * blockDim.x + threadIdx.x; // n*4 + h
    if (idx >= NN * HEADS) return;
    int n = idx >> 2;
    int h = idx & 3;
    const float4* Hp = (const float4*)(g_H + (size_t)n * DIM + h * ODIM);
    const float4* Ap = (const float4*)(Al + h * ODIM);
    const float4* Bp = (const float4*)(Ar + h * ODIM);
    float s = 0.f, t = 0.f;
#pragma unroll
    for (int i = 0; i < 8; i++) {
        float4 v = Hp[i];
        float4 a = Ap[i];
        float4 b = Bp[i];
        s += v.x * a.x + v.y * a.y + v.z * a.z + v.w * a.w;
        t += v.x * b.x + v.y * b.y + v.z * b.z + v.w * b.w;
    }
    g_Hs[idx] = s;
    g_Ht[idx] = t;
}

__device__ __forceinline__ float lrelu(float x) { return x > 0.f ? x : ALPHA * x; }

// ---------------- K3: global max over leaky-relu edge scores ----------------
__global__ void max_kernel(const int* __restrict__ ei) {
    float m = -1e30f;
    for (int e = blockIdx.x * blockDim.x + threadIdx.x; e < EE;
         e += gridDim.x * blockDim.x) {
        int src = ei[e];
        int tgt = ei[EE + e];
        float4 hs = *(const float4*)(g_Hs + (size_t)src * 4);
        float4 ht = *(const float4*)(g_Ht + (size_t)tgt * 4);
        m = fmaxf(m, lrelu(hs.x + ht.x));
        m = fmaxf(m, lrelu(hs.y + ht.y));
        m = fmaxf(m, lrelu(hs.z + ht.z));
        m = fmaxf(m, lrelu(hs.w + ht.w));
    }
#pragma unroll
    for (int o = 16; o > 0; o >>= 1)
        m = fmaxf(m, __shfl_xor_sync(0xffffffffu, m, o));
    __shared__ float sm[8];
    int lane = threadIdx.x & 31, wid = threadIdx.x >> 5;
    if (lane == 0) sm[wid] = m;
    __syncthreads();
    if (wid == 0) {
        m = (lane < (blockDim.x >> 5)) ? sm[lane] : -1e30f;
#pragma unroll
        for (int o = 4; o > 0; o >>= 1)
            m = fmaxf(m, __shfl_xor_sync(0xffffffffu, m, o));
        if (lane == 0) atomicMax(&g_maxenc, enc_f(m));
    }
}

// ---------------- K4: exp + denominator (red.v4) ----------------
__global__ void denom_kernel(const int* __restrict__ ei) {
    int e = blockIdx.x * blockDim.x + threadIdx.x;
    if (e >= EE) return;
    float gmax = dec_f(g_maxenc);
    int src = ei[e];
    int tgt = ei[EE + e];
    float4 hs = *(const float4*)(g_Hs + (size_t)src * 4);
    float4 ht = *(const float4*)(g_Ht + (size_t)tgt * 4);
    float4 x;
    x.x = __expf(lrelu(hs.x + ht.x) - gmax);
    x.y = __expf(lrelu(hs.y + ht.y) - gmax);
    x.z = __expf(lrelu(hs.z + ht.z) - gmax);
    x.w = __expf(lrelu(hs.w + ht.w) - gmax);
    *(float4*)(g_expe + (size_t)e * 4) = x;
    red_add_v4(g_denom + (size_t)src * 4, x);
}

// ---------------- K5: weighted scatter-add aggregation ----------------
// 8 threads per edge; lane j handles one float4 per head (cols h*32 + j*4 .. +3)
__global__ __launch_bounds__(256) void agg_kernel(const int* __restrict__ ei,
                                                  float* __restrict__ out) {
    long long gt = (long long)blockIdx.x * blockDim.x + threadIdx.x;
    long long e = gt >> 3;
    if (e >= EE) return;
    int l8 = (int)(gt & 7);
    int src = ei[e];
    int tgt = ei[EE + e];
    float4 ex = *(const float4*)(g_expe + (size_t)e * 4);
    float4 dn = *(const float4*)(g_denom + (size_t)src * 4);
    float a[4];
    a[0] = ex.x / (dn.x + 1e-8f);
    a[1] = ex.y / (dn.y + 1e-8f);
    a[2] = ex.z / (dn.z + 1e-8f);
    a[3] = ex.w / (dn.w + 1e-8f);
    const float* hp = g_H + (size_t)tgt * DIM;
    float* op = out + (size_t)src * DIM;
#pragma unroll
    for (int h = 0; h < 4; h++) {
        int c = h * ODIM + l8 * 4;
        float4 v = *(const float4*)(hp + c);
        v.x *= a[h]; v.y *= a[h]; v.z *= a[h]; v.w *= a[h];
        red_add_v4(op + c, v);
    }
}

// ---------------- K6: ELU epilogue ----------------
__global__ void elu_kernel(float* __restrict__ out) {
    int i = blockIdx.x * blockDim.x + threadIdx.x;
    if (i >= NN * DIM) return;
    float x = out[i];
    out[i] = x > 0.f ? x : expm1f(x);
}

extern "C" void kernel_launch(void* const* d_in, const int* in_sizes, int n_in,
                              void* d_out, int out_size) {
    const float* X  = (const float*)d_in[0];
    const int* EI   = (const int*)d_in[1];   // edge_index: int32 (JAX x64-off downcast)
    const float* W  = (const float*)d_in[2];
    const float* Al = (const float*)d_in[3];
    const float* Ar = (const float*)d_in[4];
    float* out = (float*)d_out;

    init_kernel<<<(NN * DIM + 255) / 256, 256>>>(out);
    gemm_kernel<<<(NN + 127) / 128, 256>>>(X, W);
    score_kernel<<<(NN * HEADS + 255) / 256, 256>>>(Al, Ar);
    max_kernel<<<2048, 256>>>(EI);
    denom_kernel<<<(EE + 255) / 256, 256>>>(EI);
    agg_kernel<<<(int)(((long long)EE * 8 + 255) / 256), 256>>>(EI, out);
    elu_kernel<<<(NN * DIM + 255) / 256, 256>>>(out);
}